// round 9
// baseline (speedup 1.0000x reference)
#include <cuda_runtime.h>
#include <math.h>

#define BB 64
#define HH 1024
#define BH (BB*HH)                       // 65536

// d_out layout: [c_new (B*H*H)][n_new (B*H)][m_new (B)][h (B*H)]
#define OFF_N  ((size_t)BB*(size_t)HH*(size_t)HH)
#define OFF_M  (OFF_N + (size_t)BH)
#define OFF_H  (OFF_M + (size_t)BB)

// scratch (no allocations allowed -> device globals)
__device__ __align__(16) float g_qk[BH];
__device__ __align__(16) float g_act[5 * BH];        // 0=query 1=key 2=value 3=out 4=skip

__device__ __forceinline__ unsigned f2tf(float f) {
    unsigned u;
    asm("cvt.rna.tf32.f32 %0, %1;" : "=r"(u) : "f"(f));
    return u;
}
__device__ __forceinline__ float tfbits(float f) { return __uint_as_float(f2tf(f)); }

__device__ __forceinline__ void mma_tf32(float* d, const unsigned* a, const unsigned* b) {
    asm("mma.sync.aligned.m16n8k8.row.col.f32.tf32.tf32.f32 "
        "{%0,%1,%2,%3},{%4,%5,%6,%7},{%8,%9},{%0,%1,%2,%3};"
        : "+f"(d[0]), "+f"(d[1]), "+f"(d[2]), "+f"(d[3])
        : "r"(a[0]), "r"(a[1]), "r"(a[2]), "r"(a[3]), "r"(b[0]), "r"(b[1]));
}

// ---------------------------------------------------------------------------
// GEMM body: one 64x32 output tile of activation z, full K=1024.
// BK=64, 256 threads = 8 warps (2x4), warp tile 32x8, tf32 mma.sync,
// register-prefetch pipeline, fused bias+activation epilogue -> g_act.
// ---------------------------------------------------------------------------
__device__ __forceinline__ void gemm_tile(int z, int nt,
                                          const float* __restrict__ A,
                                          const float* __restrict__ W,
                                          const float* __restrict__ bias)
{
    __shared__ float As[64][68];         // [m][k]: frag banks 4*gr+c4 (bijective)
    __shared__ float Bs[64][40];         // [k][n]: frag banks 8*c4+gr (bijective)

    const int t = threadIdx.x;
    const int lane = t & 31, warp = t >> 5;
    const int wm = (warp >> 2) * 32;     // warp row base {0,32}
    const int wn = (warp & 3) * 8;       // warp col base {0,8,16,24}
    const int gr = lane >> 2, c4 = lane & 3;

    float acc[2][4] = {};
    float4 aR[4], bR[2];

    const int arow = t >> 4, akc = (t & 15) * 4;
    const int bkr = t >> 3, bnc = (t & 7) * 4;

#pragma unroll
    for (int i = 0; i < 4; i++)
        aR[i] = *(const float4*)(A + (arow + i * 16) * HH + akc);
#pragma unroll
    for (int i = 0; i < 2; i++)
        bR[i] = *(const float4*)(W + (size_t)(bkr + i * 32) * HH + nt + bnc);

    for (int it = 0; it < 16; it++) {
#pragma unroll
        for (int i = 0; i < 4; i++)
            *(float4*)&As[arow + i * 16][akc] =
                make_float4(tfbits(aR[i].x), tfbits(aR[i].y),
                            tfbits(aR[i].z), tfbits(aR[i].w));
#pragma unroll
        for (int i = 0; i < 2; i++)
            *(float4*)&Bs[bkr + i * 32][bnc] =
                make_float4(tfbits(bR[i].x), tfbits(bR[i].y),
                            tfbits(bR[i].z), tfbits(bR[i].w));
        __syncthreads();

        if (it + 1 < 16) {
            int kt = (it + 1) * 64;
#pragma unroll
            for (int i = 0; i < 4; i++)
                aR[i] = *(const float4*)(A + (arow + i * 16) * HH + kt + akc);
#pragma unroll
            for (int i = 0; i < 2; i++)
                bR[i] = *(const float4*)(W + (size_t)(kt + bkr + i * 32) * HH + nt + bnc);
        }

#pragma unroll
        for (int kk = 0; kk < 64; kk += 8) {
            unsigned a[2][4], bfr[2];
#pragma unroll
            for (int mi = 0; mi < 2; mi++) {
                int r0 = wm + mi * 16 + gr;
                a[mi][0] = __float_as_uint(As[r0][kk + c4]);
                a[mi][1] = __float_as_uint(As[r0 + 8][kk + c4]);
                a[mi][2] = __float_as_uint(As[r0][kk + c4 + 4]);
                a[mi][3] = __float_as_uint(As[r0 + 8][kk + c4 + 4]);
            }
            bfr[0] = __float_as_uint(Bs[kk + c4][wn + gr]);
            bfr[1] = __float_as_uint(Bs[kk + c4 + 4][wn + gr]);
#pragma unroll
            for (int mi = 0; mi < 2; mi++)
                mma_tf32(acc[mi], a[mi], bfr);
        }
        __syncthreads();
    }

    float* G = g_act + (size_t)z * BH;
#pragma unroll
    for (int mi = 0; mi < 2; mi++) {
        int row = wm + mi * 16 + gr;
        int col = nt + wn + 2 * c4;
        float2 bb = *(const float2*)(bias + col);
        float v0 = acc[mi][0] + bb.x, v1 = acc[mi][1] + bb.y;
        float v2 = acc[mi][2] + bb.x, v3 = acc[mi][3] + bb.y;
        if (z == 1) { v0 *= 0.03125f; v1 *= 0.03125f; v2 *= 0.03125f; v3 *= 0.03125f; }
        if (z == 3) {
            v0 = 1.f / (1.f + expf(-v0)); v1 = 1.f / (1.f + expf(-v1));
            v2 = 1.f / (1.f + expf(-v2)); v3 = 1.f / (1.f + expf(-v3));
        }
        *(float2*)(G + (size_t)row * HH + col) = make_float2(v0, v1);
        *(float2*)(G + (size_t)(row + 8) * HH + col) = make_float2(v2, v3);
    }
}

// ---------------------------------------------------------------------------
// kP1: one launch, overlapped work.
//   y==0 : conv+silu -> g_qk (32 blocks, 2 batch rows each)
//   y==1 : value GEMM (z=2, A=x)
//   y==2 : out   GEMM (z=3, A=x)
// grid (32,3), 256 threads
// ---------------------------------------------------------------------------
__global__ void __launch_bounds__(256, 2)
kP1(const float* __restrict__ x,
    const float* __restrict__ cw, const float* __restrict__ cb,
    const float* __restrict__ Wv, const float* __restrict__ bv,
    const float* __restrict__ Wo, const float* __restrict__ bo)
{
    if (blockIdx.y == 0) {
        // conv: 2 batch rows per block. Data at xs[r][4+w] (16B-aligned base),
        // left pad at [3], right pads at [1028..1029].
        __shared__ float xs[2][1032];
        int b0 = blockIdx.x * 2, t = threadIdx.x;
#pragma unroll
        for (int r = 0; r < 2; r++) {
            float4 v = ((const float4*)(x + (b0 + r) * HH))[t];
            *(float4*)&xs[r][4 + t * 4] = v;
        }
        if (t < 2) {
            xs[t][3] = 0.f;
            xs[t][1028] = 0.f; xs[t][1029] = 0.f;
        }
        __syncthreads();
        float c0 = cw[0], c1 = cw[1], c2 = cw[2], c3 = cw[3], cbv = cb[0];
#pragma unroll
        for (int r = 0; r < 2; r++) {
#pragma unroll
            for (int j = 0; j < 4; j++) {
                int w = t * 4 + j;
                // window x[w-1..w+2] lives at xs[3+w .. 6+w]
                float v = cbv + c0 * xs[r][3 + w] + c1 * xs[r][4 + w]
                              + c2 * xs[r][5 + w] + c3 * xs[r][6 + w];
                g_qk[(b0 + r) * HH + w] = v / (1.f + expf(-v));
            }
        }
    } else if (blockIdx.y == 1) {
        gemm_tile(2, blockIdx.x * 32, x, Wv, bv);
    } else {
        gemm_tile(3, blockIdx.x * 32, x, Wo, bo);
    }
}

// ---------------------------------------------------------------------------
// kP2: qk-dependent GEMMs. y==0: query(z=0), y==1: key(z=1), y==2: skip(z=4)
// grid (32,3), 256 threads
// ---------------------------------------------------------------------------
__global__ void __launch_bounds__(256, 2)
kP2(const float* __restrict__ Wq, const float* __restrict__ bq,
    const float* __restrict__ Wk, const float* __restrict__ bk,
    const float* __restrict__ Ws, const float* __restrict__ bs)
{
    if (blockIdx.y == 0)      gemm_tile(0, blockIdx.x * 32, g_qk, Wq, bq);
    else if (blockIdx.y == 1) gemm_tile(1, blockIdx.x * 32, g_qk, Wk, bk);
    else                      gemm_tile(4, blockIdx.x * 32, g_qk, Ws, bs);
}

// ---------------------------------------------------------------------------
// kD: HBM-bound pass + gate computation. 1 row/warp, 8 streaming c-loads
// issued before the preamble math (hidden under DRAM latency).
// Gates and scaler computed per block (deterministic). rb==0 writes
// n_new, m_new. grid: (128, 64), block 256
// ---------------------------------------------------------------------------
__global__ void __launch_bounds__(256, 3)
kD(const float* __restrict__ c, const float* __restrict__ n,
   const float* __restrict__ x,
   const float* __restrict__ Wi, const float* __restrict__ bi,
   const float* __restrict__ Wf, const float* __restrict__ bf,
   const float* __restrict__ m, float* __restrict__ out)
{
    __shared__ float ks[HH];
    __shared__ float qs[HH];
    __shared__ float red[32];
    int rb = blockIdx.x, b = blockIdx.y;
    int t = threadIdx.x, lane = t & 31, wid = t >> 5;

    const int i = rb * 8 + wid;                       // this warp's row
    const size_t base = ((size_t)b * HH + i) * (size_t)HH;

    // issue the streaming loads first: preamble hides under their latency
    float4 cv[8];
#pragma unroll
    for (int j = 0; j < 8; j++)
        cv[j] = __ldcs((const float4*)(c + base + j * 128 + lane * 4));

    float4 k4 = ((const float4*)(g_act + 1 * BH + b * HH))[t];
    float4 q4 = ((const float4*)(g_act + 0 * BH + b * HH))[t];
    float4 n4 = ((const float4*)(n + b * HH))[t];
    float4 x4 = ((const float4*)(x + b * HH))[t];
    float4 wi4 = ((const float4*)Wi)[t];
    float4 wf4 = ((const float4*)Wf)[t];
    ((float4*)ks)[t] = k4;
    ((float4*)qs)[t] = q4;

    float pkq = k4.x * q4.x + k4.y * q4.y + k4.z * q4.z + k4.w * q4.w;
    float pnq = n4.x * q4.x + n4.y * q4.y + n4.z * q4.z + n4.w * q4.w;
    float pi  = x4.x * wi4.x + x4.y * wi4.y + x4.z * wi4.z + x4.w * wi4.w;
    float pf  = x4.x * wf4.x + x4.y * wf4.y + x4.z * wf4.z + x4.w * wf4.w;
#pragma unroll
    for (int o = 16; o; o >>= 1) {
        pkq += __shfl_xor_sync(~0u, pkq, o);
        pnq += __shfl_xor_sync(~0u, pnq, o);
        pi  += __shfl_xor_sync(~0u, pi, o);
        pf  += __shfl_xor_sync(~0u, pf, o);
    }
    if (lane == 0) {
        red[wid] = pkq; red[8 + wid] = pnq;
        red[16 + wid] = pi; red[24 + wid] = pf;
    }
    __syncthreads();

    float kq = 0.f, nq = 0.f, itil = bi[0], ftil = bf[0];
#pragma unroll
    for (int w = 0; w < 8; w++) {
        kq += red[w]; nq += red[8 + w];
        itil += red[16 + w]; ftil += red[24 + w];
    }
    float mb = m[b];
    float mn = fmaxf(ftil + mb, itil);
    float ig = expf(itil - mn);
    float fg = expf(ftil + mb - mn);
    float sc = 1.f / fmaxf(fabsf(fg * nq + ig * kq), 1.f);

    if (rb == 0) {   // write n_new and m_new for this batch
        float4 nn;
        nn.x = fg * n4.x + ig * k4.x;
        nn.y = fg * n4.y + ig * k4.y;
        nn.z = fg * n4.z + ig * k4.z;
        nn.w = fg * n4.w + ig * k4.w;
        ((float4*)(out + OFF_N + (size_t)b * HH))[t] = nn;
        if (t == 0) out[OFF_M + b] = mn;
    }

    const float igv = ig * g_act[2 * BH + b * HH + i];
    float acc = 0.f;
#pragma unroll
    for (int j = 0; j < 8; j++) {
        int k0 = j * 128 + lane * 4;
        float4 kk = *(float4*)(ks + k0);
        float4 qq = *(float4*)(qs + k0);
        float4 r;
        r.x = fg * cv[j].x + igv * kk.x;
        r.y = fg * cv[j].y + igv * kk.y;
        r.z = fg * cv[j].z + igv * kk.z;
        r.w = fg * cv[j].w + igv * kk.w;
        __stcs((float4*)(out + base + k0), r);
        acc += r.x * qq.x + r.y * qq.y + r.z * qq.z + r.w * qq.w;
    }
#pragma unroll
    for (int o = 16; o; o >>= 1) acc += __shfl_xor_sync(~0u, acc, o);
    if (lane == 0) {
        out[OFF_H + (size_t)b * HH + i] =
            g_act[3 * BH + b * HH + i] * (acc * sc) + g_act[4 * BH + b * HH + i];
    }
}

// ---------------------------------------------------------------------------
extern "C" void kernel_launch(void* const* d_in, const int* in_sizes, int n_in,
                              void* d_out, int out_size)
{
    (void)in_sizes; (void)n_in; (void)out_size;
    const float* c      = (const float*)d_in[0];
    const float* n      = (const float*)d_in[1];
    const float* m      = (const float*)d_in[2];
    const float* x      = (const float*)d_in[3];
    const float* Wq     = (const float*)d_in[4];
    const float* bq     = (const float*)d_in[5];
    const float* Wk     = (const float*)d_in[6];
    const float* bk     = (const float*)d_in[7];
    const float* Wv     = (const float*)d_in[8];
    const float* bv     = (const float*)d_in[9];
    const float* conv_w = (const float*)d_in[10];
    const float* conv_b = (const float*)d_in[11];
    const float* Wi     = (const float*)d_in[12];
    const float* bi     = (const float*)d_in[13];
    const float* Wf     = (const float*)d_in[14];
    const float* bf     = (const float*)d_in[15];
    const float* Wo     = (const float*)d_in[16];
    const float* bo     = (const float*)d_in[17];
    const float* Wskip  = (const float*)d_in[18];
    const float* bskip  = (const float*)d_in[19];
    float* out = (float*)d_out;

    kP1<<<dim3(32, 3), 256>>>(x, conv_w, conv_b, Wv, bv, Wo, bo);
    kP2<<<dim3(32, 3), 256>>>(Wq, bq, Wk, bk, Wskip, bskip);
    kD<<<dim3(128, 64), 256>>>(c, n, x, Wi, bi, Wf, bf, m, out);
}

// round 10
// speedup vs baseline: 1.1278x; 1.1278x over previous
#include <cuda_runtime.h>
#include <math.h>

#define BB 64
#define HH 1024
#define BH (BB*HH)                       // 65536
#define SK 4                             // split-K factor

// d_out layout: [c_new (B*H*H)][n_new (B*H)][m_new (B)][h (B*H)]
#define OFF_N  ((size_t)BB*(size_t)HH*(size_t)HH)
#define OFF_M  (OFF_N + (size_t)BH)
#define OFF_H  (OFF_M + (size_t)BB)

// scratch (no allocations allowed -> device globals)
__device__ __align__(16) float g_qk[BH];
__device__ __align__(16) float g_part[SK * 5 * BH];  // split-K partials
__device__ __align__(16) float g_act[5 * BH];        // 0=query 1=key 2=value 3=out 4=skip

__device__ __forceinline__ unsigned f2tf(float f) {
    unsigned u;
    asm("cvt.rna.tf32.f32 %0, %1;" : "=r"(u) : "f"(f));
    return u;
}
__device__ __forceinline__ float tfbits(float f) { return __uint_as_float(f2tf(f)); }

__device__ __forceinline__ void mma_tf32(float* d, const unsigned* a, const unsigned* b) {
    asm("mma.sync.aligned.m16n8k8.row.col.f32.tf32.tf32.f32 "
        "{%0,%1,%2,%3},{%4,%5,%6,%7},{%8,%9},{%0,%1,%2,%3};"
        : "+f"(d[0]), "+f"(d[1]), "+f"(d[2]), "+f"(d[3])
        : "r"(a[0]), "r"(a[1]), "r"(a[2]), "r"(a[3]), "r"(b[0]), "r"(b[1]));
}

// ---------------------------------------------------------------------------
// Split-K GEMM tile (R5-proven body): one 64x64 tile, K range [kz*256, +256),
// 128 threads = 4 warps (2x2), warp tile 32x32, tf32 mma.sync.
// Writes partial to g_part[(kz*5+z)*BH].
// ---------------------------------------------------------------------------
__device__ __forceinline__ void gemm_sk(int z, int nt, int kz,
                                        const float* __restrict__ A,
                                        const float* __restrict__ W)
{
    __shared__ float As[64][36];         // [m][k]: frag banks 4*gr+c4 (bijective)
    __shared__ float Bs[32][72];         // [k][n]: frag banks 8*c4+gr (bijective)

    const int t = threadIdx.x;
    const int lane = t & 31, warp = t >> 5;
    const int wm = (warp >> 1) * 32;     // warp row base
    const int wn = (warp & 1) * 32;      // warp col base
    const int gr = lane >> 2, c4 = lane & 3;

    float acc[2][4][4] = {};

    const int kbeg = kz * (HH / SK), kend = kbeg + (HH / SK);
    for (int kt = kbeg; kt < kend; kt += 32) {
#pragma unroll
        for (int i = 0; i < 4; i++) {
            int f = t + i * 128;
            int row = f >> 3, kc = (f & 7) * 4;
            float4 v = *(const float4*)(A + row * HH + kt + kc);
            As[row][kc + 0] = __uint_as_float(f2tf(v.x));
            As[row][kc + 1] = __uint_as_float(f2tf(v.y));
            As[row][kc + 2] = __uint_as_float(f2tf(v.z));
            As[row][kc + 3] = __uint_as_float(f2tf(v.w));
        }
#pragma unroll
        for (int i = 0; i < 4; i++) {
            int f = t + i * 128;
            int kr = f >> 4, nc = (f & 15) * 4;
            float4 v = *(const float4*)(W + (size_t)(kt + kr) * HH + nt + nc);
            *(float4*)&Bs[kr][nc] =
                make_float4(tfbits(v.x), tfbits(v.y), tfbits(v.z), tfbits(v.w));
        }
        __syncthreads();
#pragma unroll
        for (int kk = 0; kk < 32; kk += 8) {
            unsigned a[2][4], bf2[4][2];
#pragma unroll
            for (int mi = 0; mi < 2; mi++) {
                int r0 = wm + mi * 16 + gr;
                a[mi][0] = __float_as_uint(As[r0][kk + c4]);
                a[mi][1] = __float_as_uint(As[r0 + 8][kk + c4]);
                a[mi][2] = __float_as_uint(As[r0][kk + c4 + 4]);
                a[mi][3] = __float_as_uint(As[r0 + 8][kk + c4 + 4]);
            }
#pragma unroll
            for (int ni = 0; ni < 4; ni++) {
                int ncol = wn + ni * 8 + gr;
                bf2[ni][0] = __float_as_uint(Bs[kk + c4][ncol]);
                bf2[ni][1] = __float_as_uint(Bs[kk + c4 + 4][ncol]);
            }
#pragma unroll
            for (int mi = 0; mi < 2; mi++)
#pragma unroll
                for (int ni = 0; ni < 4; ni++)
                    mma_tf32(acc[mi][ni], a[mi], bf2[ni]);
        }
        __syncthreads();
    }

    float* P = g_part + (size_t)(kz * 5 + z) * BH;
#pragma unroll
    for (int mi = 0; mi < 2; mi++) {
        int row = wm + mi * 16 + gr;
#pragma unroll
        for (int ni = 0; ni < 4; ni++) {
            int col = nt + wn + ni * 8 + 2 * c4;
            *(float2*)(P + (size_t)row * HH + col) =
                make_float2(acc[mi][ni][0], acc[mi][ni][1]);
            *(float2*)(P + (size_t)(row + 8) * HH + col) =
                make_float2(acc[mi][ni][2], acc[mi][ni][3]);
        }
    }
}

// ---------------------------------------------------------------------------
// kP1: conv (64 blocks) + value/out split-K GEMMs (128 blocks). 128 threads.
// ---------------------------------------------------------------------------
__global__ void __launch_bounds__(128, 4)
kP1(const float* __restrict__ x,
    const float* __restrict__ cw, const float* __restrict__ cb,
    const float* __restrict__ Wv, const float* __restrict__ Wo)
{
    int bx = blockIdx.x;
    if (bx < 64) {
        // conv+silu for batch row bx. Data at xs[4+p] (16B-aligned), pads zeroed.
        __shared__ float xs[1032];
        int t = threadIdx.x;
        float4 v0 = ((const float4*)(x + bx * HH))[t];
        float4 v1 = ((const float4*)(x + bx * HH))[t + 128];
        *(float4*)&xs[4 + t * 4] = v0;
        *(float4*)&xs[4 + (t + 128) * 4] = v1;
        if (t == 0) { xs[3] = 0.f; xs[1028] = 0.f; xs[1029] = 0.f; }
        __syncthreads();
        float c0 = cw[0], c1 = cw[1], c2 = cw[2], c3 = cw[3], cbv = cb[0];
#pragma unroll
        for (int h = 0; h < 2; h++) {
#pragma unroll
            for (int j = 0; j < 4; j++) {
                int w = (t + h * 128) * 4 + j;
                float v = cbv + c0 * xs[3 + w] + c1 * xs[4 + w]
                              + c2 * xs[5 + w] + c3 * xs[6 + w];
                g_qk[bx * HH + w] = v / (1.f + expf(-v));
            }
        }
    } else {
        int g = bx - 64;                 // 0..127
        int mat = g >> 6;                // 0:value 1:out
        int r = g & 63;
        int nt = (r >> 2) * 64, kz = r & 3;
        gemm_sk(mat == 0 ? 2 : 3, nt, kz, x, mat == 0 ? Wv : Wo);
    }
}

// ---------------------------------------------------------------------------
// kP2: q/key/skip split-K GEMMs on g_qk. 192 blocks, 128 threads.
// ---------------------------------------------------------------------------
__global__ void __launch_bounds__(128, 4)
kP2(const float* __restrict__ Wq, const float* __restrict__ Wk,
    const float* __restrict__ Ws)
{
    int g = blockIdx.x;
    int mat = g >> 6;                    // 0:query 1:key 2:skip
    int r = g & 63;
    int nt = (r >> 2) * 64, kz = r & 3;
    int z = (mat == 2) ? 4 : mat;
    const float* W = (mat == 0) ? Wq : (mat == 1) ? Wk : Ws;
    gemm_sk(z, nt, kz, g_qk, W);
}

// ---------------------------------------------------------------------------
// kEpi: pure reduce: sum SK partials + bias + activation -> g_act.
// grid 320 x 256
// ---------------------------------------------------------------------------
__global__ void kEpi(const float* __restrict__ bq, const float* __restrict__ bk,
                     const float* __restrict__ bv, const float* __restrict__ bo,
                     const float* __restrict__ bs)
{
    int idx = blockIdx.x * 256 + threadIdx.x;   // float4 index
    int e = idx * 4;
    int z = e >> 16;
    int i = e & (BH - 1);
    int col = i & (HH - 1);
    const float* bias = (z == 0) ? bq : (z == 1) ? bk : (z == 2) ? bv : (z == 3) ? bo : bs;

    float4 v = *(const float4*)(g_part + (size_t)z * BH + i);
#pragma unroll
    for (int s = 1; s < SK; s++) {
        float4 p = *(const float4*)(g_part + (size_t)(s * 5 + z) * BH + i);
        v.x += p.x; v.y += p.y; v.z += p.z; v.w += p.w;
    }
    float4 bb = *(const float4*)(bias + col);
    v.x += bb.x; v.y += bb.y; v.z += bb.z; v.w += bb.w;
    if (z == 1) { v.x *= 0.03125f; v.y *= 0.03125f; v.z *= 0.03125f; v.w *= 0.03125f; }
    if (z == 3) {
        v.x = 1.f / (1.f + expf(-v.x)); v.y = 1.f / (1.f + expf(-v.y));
        v.z = 1.f / (1.f + expf(-v.z)); v.w = 1.f / (1.f + expf(-v.w));
    }
    *(float4*)(g_act + (size_t)z * BH + i) = v;
}

// ---------------------------------------------------------------------------
// kD: HBM-bound pass + gate computation (R7/R9-proven). 1 row/warp,
// 8 streaming c-loads issued before the preamble math.
// rb==0 writes n_new, m_new. grid: (128, 64), block 256
// ---------------------------------------------------------------------------
__global__ void __launch_bounds__(256, 3)
kD(const float* __restrict__ c, const float* __restrict__ n,
   const float* __restrict__ x,
   const float* __restrict__ Wi, const float* __restrict__ bi,
   const float* __restrict__ Wf, const float* __restrict__ bf,
   const float* __restrict__ m, float* __restrict__ out)
{
    __shared__ float ks[HH];
    __shared__ float qs[HH];
    __shared__ float red[32];
    int rb = blockIdx.x, b = blockIdx.y;
    int t = threadIdx.x, lane = t & 31, wid = t >> 5;

    const int i = rb * 8 + wid;                       // this warp's row
    const size_t base = ((size_t)b * HH + i) * (size_t)HH;

    // issue the streaming loads first: preamble hides under their latency
    float4 cv[8];
#pragma unroll
    for (int j = 0; j < 8; j++)
        cv[j] = __ldcs((const float4*)(c + base + j * 128 + lane * 4));

    float4 k4 = ((const float4*)(g_act + 1 * BH + b * HH))[t];
    float4 q4 = ((const float4*)(g_act + 0 * BH + b * HH))[t];
    float4 n4 = ((const float4*)(n + b * HH))[t];
    float4 x4 = ((const float4*)(x + b * HH))[t];
    float4 wi4 = ((const float4*)Wi)[t];
    float4 wf4 = ((const float4*)Wf)[t];
    ((float4*)ks)[t] = k4;
    ((float4*)qs)[t] = q4;

    float pkq = k4.x * q4.x + k4.y * q4.y + k4.z * q4.z + k4.w * q4.w;
    float pnq = n4.x * q4.x + n4.y * q4.y + n4.z * q4.z + n4.w * q4.w;
    float pi  = x4.x * wi4.x + x4.y * wi4.y + x4.z * wi4.z + x4.w * wi4.w;
    float pf  = x4.x * wf4.x + x4.y * wf4.y + x4.z * wf4.z + x4.w * wf4.w;
#pragma unroll
    for (int o = 16; o; o >>= 1) {
        pkq += __shfl_xor_sync(~0u, pkq, o);
        pnq += __shfl_xor_sync(~0u, pnq, o);
        pi  += __shfl_xor_sync(~0u, pi, o);
        pf  += __shfl_xor_sync(~0u, pf, o);
    }
    if (lane == 0) {
        red[wid] = pkq; red[8 + wid] = pnq;
        red[16 + wid] = pi; red[24 + wid] = pf;
    }
    __syncthreads();

    float kq = 0.f, nq = 0.f, itil = bi[0], ftil = bf[0];
#pragma unroll
    for (int w = 0; w < 8; w++) {
        kq += red[w]; nq += red[8 + w];
        itil += red[16 + w]; ftil += red[24 + w];
    }
    float mb = m[b];
    float mn = fmaxf(ftil + mb, itil);
    float ig = expf(itil - mn);
    float fg = expf(ftil + mb - mn);
    float sc = 1.f / fmaxf(fabsf(fg * nq + ig * kq), 1.f);

    if (rb == 0) {   // write n_new and m_new for this batch
        float4 nn;
        nn.x = fg * n4.x + ig * k4.x;
        nn.y = fg * n4.y + ig * k4.y;
        nn.z = fg * n4.z + ig * k4.z;
        nn.w = fg * n4.w + ig * k4.w;
        ((float4*)(out + OFF_N + (size_t)b * HH))[t] = nn;
        if (t == 0) out[OFF_M + b] = mn;
    }

    const float igv = ig * g_act[2 * BH + b * HH + i];
    float acc = 0.f;
#pragma unroll
    for (int j = 0; j < 8; j++) {
        int k0 = j * 128 + lane * 4;
        float4 kk = *(float4*)(ks + k0);
        float4 qq = *(float4*)(qs + k0);
        float4 r;
        r.x = fg * cv[j].x + igv * kk.x;
        r.y = fg * cv[j].y + igv * kk.y;
        r.z = fg * cv[j].z + igv * kk.z;
        r.w = fg * cv[j].w + igv * kk.w;
        __stcs((float4*)(out + base + k0), r);
        acc += r.x * qq.x + r.y * qq.y + r.z * qq.z + r.w * qq.w;
    }
#pragma unroll
    for (int o = 16; o; o >>= 1) acc += __shfl_xor_sync(~0u, acc, o);
    if (lane == 0) {
        out[OFF_H + (size_t)b * HH + i] =
            g_act[3 * BH + b * HH + i] * (acc * sc) + g_act[4 * BH + b * HH + i];
    }
}

// ---------------------------------------------------------------------------
extern "C" void kernel_launch(void* const* d_in, const int* in_sizes, int n_in,
                              void* d_out, int out_size)
{
    (void)in_sizes; (void)n_in; (void)out_size;
    const float* c      = (const float*)d_in[0];
    const float* n      = (const float*)d_in[1];
    const float* m      = (const float*)d_in[2];
    const float* x      = (const float*)d_in[3];
    const float* Wq     = (const float*)d_in[4];
    const float* bq     = (const float*)d_in[5];
    const float* Wk     = (const float*)d_in[6];
    const float* bk     = (const float*)d_in[7];
    const float* Wv     = (const float*)d_in[8];
    const float* bv     = (const float*)d_in[9];
    const float* conv_w = (const float*)d_in[10];
    const float* conv_b = (const float*)d_in[11];
    const float* Wi     = (const float*)d_in[12];
    const float* bi     = (const float*)d_in[13];
    const float* Wf     = (const float*)d_in[14];
    const float* bf     = (const float*)d_in[15];
    const float* Wo     = (const float*)d_in[16];
    const float* bo     = (const float*)d_in[17];
    const float* Wskip  = (const float*)d_in[18];
    const float* bskip  = (const float*)d_in[19];
    float* out = (float*)d_out;

    kP1<<<192, 128>>>(x, conv_w, conv_b, Wv, Wo);
    kP2<<<192, 128>>>(Wq, Wk, Wskip);
    kEpi<<<320, 256>>>(bq, bk, bv, bo, bskip);
    kD<<<dim3(128, 64), 256>>>(c, n, x, Wi, bi, Wf, bf, m, out);
}